// round 2
// baseline (speedup 1.0000x reference)
#include <cuda_runtime.h>

// ---------------- problem constants ----------------
#define NF   133
#define EFE  14
#define HH   300
#define GG   200
#define TT   12
#define NLAYERS 3
#define BB   4096
#define NPER 32
#define NPAIRS 32
#define NNODE (BB*NPER)      // 131072
#define EEDGE (BB*NPAIRS*2)  // 262144
#define RR1  550
#define RR2  378

// ---------------- scratch (static device allocations) ----------------
__device__ float g_h0 [(size_t)EEDGE*HH];
__device__ float g_b1 [(size_t)EEDGE*HH];
__device__ float g_b2 [(size_t)EEDGE*HH];
__device__ float g_me [(size_t)EEDGE*HH];
__device__ float g_mv [(size_t)NNODE*HH];
__device__ float g_hv [(size_t)NNODE*HH];
__device__ float g_o0 [(size_t)BB*HH];
__device__ float g_r1 [(size_t)BB*RR1];
__device__ float g_r2 [(size_t)BB*RR2];

// ---------------- A-tile loaders (fuse gather/concat into GEMM) ----------------
struct LdPlain {
    const float* A; int lda;
    __device__ __forceinline__ float operator()(int r, int k) const {
        return A[(size_t)r * lda + k];
    }
};
// row e of [ vv[src[e]] | ee[e] ]  (K = 147)
struct LdH0 {
    const float* v; const float* e; const int* src;
    __device__ __forceinline__ float operator()(int r, int k) const {
        if (k < NF) { int s = src[r]; return v[(size_t)s * (NF+1) + k]; }
        return e[(size_t)r * (EFE+1) + (k - NF)];
    }
};
// row n of [ vv[n] | m_v[n] ]  (K = 433)
struct LdHv {
    const float* v; const float* mv;
    __device__ __forceinline__ float operator()(int r, int k) const {
        if (k < NF) return v[(size_t)r * (NF+1) + k];
        return mv[(size_t)r * HH + (k - NF)];
    }
};
// row b of [ out0[b] | globals[b] ]  (K = 500)
struct LdR1 {
    const float* o; const float* g;
    __device__ __forceinline__ float operator()(int r, int k) const {
        if (k < HH) return o[(size_t)r * HH + k];
        return g[(size_t)r * GG + (k - HH)];
    }
};

// ---------------- generic tiled fp32 GEMM ----------------
// C[M,N] = act( A[M,K] @ W[K,N] + bias + (resid?) )
// BM=128, BN=64, BK=16, 256 threads, 8x4 per thread. M must be divisible by 128.
template<class L>
__global__ void __launch_bounds__(256)
gemm_k(L loader, const float* __restrict__ W,
       const float* __restrict__ bias, const float* __restrict__ resid,
       float* __restrict__ C, int N, int K, int relu_flag)
{
    constexpr int BM = 128, BN = 64, BK = 16;
    __shared__ float As[BK][BM + 1];   // +1 pad: stride 129 -> conflict-free stores
    __shared__ float Bs[BK][BN + 4];   // +4 pad keeps float4 alignment

    const int tid  = threadIdx.x;
    const int row0 = blockIdx.x * BM;
    const int col0 = blockIdx.y * BN;
    const int tm   = tid >> 4;     // 0..15  (8 rows each)
    const int tn   = tid & 15;     // 0..15  (4 cols each)

    float acc[8][4];
    #pragma unroll
    for (int i = 0; i < 8; i++)
        #pragma unroll
        for (int j = 0; j < 4; j++) acc[i][j] = 0.f;

    for (int kt = 0; kt < K; kt += BK) {
        // load A tile: 128x16 = 2048 elems, 8 per thread
        #pragma unroll
        for (int t = 0; t < (BM * BK) / 256; t++) {
            int idx = tid + t * 256;
            int m  = idx >> 4;        // idx / BK
            int kk = idx & (BK - 1);
            float a = 0.f;
            if (kt + kk < K) a = loader(row0 + m, kt + kk);
            As[kk][m] = a;
        }
        // load W tile: 16x64 = 1024 elems, 4 per thread (coalesced over n)
        #pragma unroll
        for (int t = 0; t < (BK * BN) / 256; t++) {
            int idx = tid + t * 256;
            int kk = idx >> 6;        // idx / BN
            int n  = idx & (BN - 1);
            float bv = 0.f;
            if (kt + kk < K && col0 + n < N) bv = W[(size_t)(kt + kk) * N + col0 + n];
            Bs[kk][n] = bv;
        }
        __syncthreads();

        #pragma unroll
        for (int kk = 0; kk < BK; kk++) {
            float a[8];
            #pragma unroll
            for (int i = 0; i < 8; i++) a[i] = As[kk][tm * 8 + i];
            float4 b4 = *reinterpret_cast<const float4*>(&Bs[kk][tn * 4]);
            float b[4] = {b4.x, b4.y, b4.z, b4.w};
            #pragma unroll
            for (int i = 0; i < 8; i++)
                #pragma unroll
                for (int j = 0; j < 4; j++)
                    acc[i][j] += a[i] * b[j];
        }
        __syncthreads();
    }

    #pragma unroll
    for (int i = 0; i < 8; i++) {
        int r = row0 + tm * 8 + i;
        #pragma unroll
        for (int j = 0; j < 4; j++) {
            int c = col0 + tn * 4 + j;
            if (c < N) {
                float val = acc[i][j] + bias[c];
                if (resid) val += resid[(size_t)r * N + c];
                if (relu_flag) val = fmaxf(val, 0.f);
                C[(size_t)r * N + c] = val;
            }
        }
    }
}

// ---------------- per-graph message kernel ----------------
// One CTA per graph (64 edges, 32 nodes). Computes, fully in SMEM:
//   acc[n] = sum_{e: dst==n} h[e];   me[e] = acc[src[e]] - h[e^1]
#define MSG_CH 100   // column chunk (300 = 3 chunks)
__global__ void __launch_bounds__(256)
msg_kernel(const float* __restrict__ h, const int* __restrict__ src,
           const int* __restrict__ dst, float* __restrict__ me)
{
    __shared__ int s_src[64], s_dst[64];
    __shared__ float h_s[64 * MSG_CH];
    __shared__ float acc_s[32 * MSG_CH];
    const int b = blockIdx.x, tid = threadIdx.x;
    if (tid < 64) {
        s_src[tid] = src[b * 64 + tid] - b * 32;
        s_dst[tid] = dst[b * 64 + tid] - b * 32;
    }
    for (int c0 = 0; c0 < HH; c0 += MSG_CH) {
        __syncthreads();
        for (int idx = tid; idx < 64 * MSG_CH; idx += 256) {
            int e = idx / MSG_CH, c = idx - e * MSG_CH;
            h_s[idx] = h[(size_t)(b * 64 + e) * HH + c0 + c];
        }
        for (int idx = tid; idx < 32 * MSG_CH; idx += 256) acc_s[idx] = 0.f;
        __syncthreads();
        for (int idx = tid; idx < 64 * MSG_CH; idx += 256) {
            int e = idx / MSG_CH, c = idx - e * MSG_CH;
            atomicAdd(&acc_s[s_dst[e] * MSG_CH + c], h_s[idx]);
        }
        __syncthreads();
        for (int idx = tid; idx < 64 * MSG_CH; idx += 256) {
            int e = idx / MSG_CH, c = idx - e * MSG_CH;
            me[(size_t)(b * 64 + e) * HH + c0 + c] =
                acc_s[s_src[e] * MSG_CH + c] - h_s[(e ^ 1) * MSG_CH + c];
        }
    }
}

// m_v[n] = sum_{e: src==n} h[e]   (same per-graph structure)
__global__ void __launch_bounds__(256)
mv_kernel(const float* __restrict__ h, const int* __restrict__ src,
          float* __restrict__ mv)
{
    __shared__ int s_src[64];
    __shared__ float h_s[64 * MSG_CH];
    __shared__ float acc_s[32 * MSG_CH];
    const int b = blockIdx.x, tid = threadIdx.x;
    if (tid < 64) s_src[tid] = src[b * 64 + tid] - b * 32;
    for (int c0 = 0; c0 < HH; c0 += MSG_CH) {
        __syncthreads();
        for (int idx = tid; idx < 64 * MSG_CH; idx += 256) {
            int e = idx / MSG_CH, c = idx - e * MSG_CH;
            h_s[idx] = h[(size_t)(b * 64 + e) * HH + c0 + c];
        }
        for (int idx = tid; idx < 32 * MSG_CH; idx += 256) acc_s[idx] = 0.f;
        __syncthreads();
        for (int idx = tid; idx < 64 * MSG_CH; idx += 256) {
            int e = idx / MSG_CH, c = idx - e * MSG_CH;
            atomicAdd(&acc_s[s_src[e] * MSG_CH + c], h_s[idx]);
        }
        __syncthreads();
        for (int idx = tid; idx < 32 * MSG_CH; idx += 256) {
            int n = idx / MSG_CH, c = idx - n * MSG_CH;
            mv[(size_t)(b * 32 + n) * HH + c0 + c] = acc_s[idx];
        }
    }
}

// out0[b] = mean over the graph's 32 nodes of h_v  (cnt == 32 exactly)
__global__ void __launch_bounds__(256)
mean_kernel(const float* __restrict__ hv, float* __restrict__ o0)
{
    const int b = blockIdx.x;
    for (int c = threadIdx.x; c < HH; c += 256) {
        float s = 0.f;
        #pragma unroll 8
        for (int i = 0; i < NPER; i++)
            s += hv[(size_t)(b * NPER + i) * HH + c];
        o0[(size_t)b * HH + c] = s * (1.0f / NPER);
    }
}

// ---------------- launch ----------------
extern "C" void kernel_launch(void* const* d_in, const int* in_sizes, int n_in,
                              void* d_out, int out_size)
{
    (void)in_sizes; (void)n_in; (void)out_size;
    const float* v   = (const float*)d_in[0];
    const float* e   = (const float*)d_in[1];
    const float* gl  = (const float*)d_in[2];
    const float* Wi  = (const float*)d_in[3];
    const float* bi  = (const float*)d_in[4];
    const float* Wm  = (const float*)d_in[5];
    const float* bm  = (const float*)d_in[6];
    const float* Wa  = (const float*)d_in[7];
    const float* ba  = (const float*)d_in[8];
    const float* Wr1 = (const float*)d_in[9];
    const float* br1 = (const float*)d_in[10];
    const float* Wr2 = (const float*)d_in[11];
    const float* br2 = (const float*)d_in[12];
    const float* Wr3 = (const float*)d_in[13];
    const float* br3 = (const float*)d_in[14];
    const int*   src = (const int*)d_in[15];
    const int*   dst = (const int*)d_in[16];
    float* out = (float*)d_out;

    float *h0, *b1, *b2, *me, *mv, *hv, *o0, *r1, *r2;
    cudaGetSymbolAddress((void**)&h0, g_h0);
    cudaGetSymbolAddress((void**)&b1, g_b1);
    cudaGetSymbolAddress((void**)&b2, g_b2);
    cudaGetSymbolAddress((void**)&me, g_me);
    cudaGetSymbolAddress((void**)&mv, g_mv);
    cudaGetSymbolAddress((void**)&hv, g_hv);
    cudaGetSymbolAddress((void**)&o0, g_o0);
    cudaGetSymbolAddress((void**)&r1, g_r1);
    cudaGetSymbolAddress((void**)&r2, g_r2);

    dim3 blk(256);
    const int NT = (HH + 63) / 64;   // 5 N-tiles for N=300

    // 1) h0 = relu([vv[src]|ee] @ Wi + bi)
    gemm_k<<<dim3(EEDGE / 128, NT), blk>>>(LdH0{v, e, src}, Wi, bi, nullptr,
                                           h0, HH, NF + EFE, 1);

    // 2) 3 message-passing layers: h = relu(h0 + (acc[src]-h[rev]) @ Wm + bm)
    const float* hin = h0;
    float* houts[NLAYERS] = {b1, b2, b1};
    for (int l = 0; l < NLAYERS; l++) {
        msg_kernel<<<BB, blk>>>(hin, src, dst, me);
        gemm_k<<<dim3(EEDGE / 128, NT), blk>>>(LdPlain{me, HH}, Wm, bm, h0,
                                               houts[l], HH, HH, 1);
        hin = houts[l];
    }

    // 3) node aggregation + node MLP
    mv_kernel<<<BB, blk>>>(hin, src, mv);
    gemm_k<<<dim3(NNODE / 128, NT), blk>>>(LdHv{v, mv}, Wa, ba, nullptr,
                                           hv, HH, NF + HH, 1);

    // 4) graph mean
    mean_kernel<<<BB, blk>>>(hv, o0);

    // 5) readout MLP
    gemm_k<<<dim3(BB / 128, (RR1 + 63) / 64), blk>>>(LdR1{o0, gl}, Wr1, br1, nullptr,
                                                     r1, RR1, HH + GG, 1);
    gemm_k<<<dim3(BB / 128, (RR2 + 63) / 64), blk>>>(LdPlain{r1, RR1}, Wr2, br2, nullptr,
                                                     r2, RR2, RR1, 1);
    gemm_k<<<dim3(BB / 128, 1), blk>>>(LdPlain{r2, RR2}, Wr3, br3, nullptr,
                                       out, TT, RR2, 0);
}

// round 5
// speedup vs baseline: 2.5022x; 2.5022x over previous
#include <cuda_runtime.h>
#include <cuda_bf16.h>
#include <cstdint>

// ---------------- problem constants ----------------
#define NF   133
#define EFE  14
#define HH   300
#define GG   200
#define TT   12
#define BB   4096
#define NPER 32
#define NNODE (BB*NPER)      // 131072
#define EEDGE (BB*64)        // 262144
#define RR1  550
#define RR2  378

// padded K per GEMM (multiple of 64); P = K-panels of 64
#define KP_H0 192   // K=147, P=3
#define KP_L  320   // K=300, P=5
#define KP_HV 448   // K=433, P=7
#define KP_R1 512   // K=500, P=8
#define KP_R2 576   // K=550, P=9
#define KP_R3 384   // K=378, P=6

// N-tile width (per CTA) is fixed at 64.
#define NT_H  5     // ceil(300/64) -> 320
#define NT_R1 9     // 576
#define NT_R2 6     // 384
#define NT_R3 1     // 64

// ---------------- scratch ----------------
__device__ float g_h0[(size_t)EEDGE*HH];
__device__ float g_hA[(size_t)EEDGE*HH];
__device__ float g_hB[(size_t)EEDGE*HH];
__device__ float g_mv[(size_t)NNODE*HH];
__device__ float g_hv[(size_t)NNODE*HH];
__device__ float g_r1[(size_t)BB*RR1];
__device__ float g_r2[(size_t)BB*RR2];

__device__ __nv_bfloat16 g_Ae [(size_t)EEDGE*2*KP_L];
__device__ __nv_bfloat16 g_Ahv[(size_t)NNODE*2*KP_HV];
__device__ __nv_bfloat16 g_Ar1[(size_t)BB*2*KP_R1];
__device__ __nv_bfloat16 g_Ar2[(size_t)BB*2*KP_R2];
__device__ __nv_bfloat16 g_Ar3[(size_t)BB*2*KP_R3];

// W panels: [ntile][3P][64 rows x 128B] swizzled bf16
__device__ __nv_bfloat16 g_Wi [(size_t)NT_H *9 *64*64];
__device__ __nv_bfloat16 g_Wm [(size_t)NT_H *15*64*64];
__device__ __nv_bfloat16 g_Wa [(size_t)NT_H *21*64*64];
__device__ __nv_bfloat16 g_Wr1[(size_t)NT_R1*24*64*64];
__device__ __nv_bfloat16 g_Wr2[(size_t)NT_R2*27*64*64];
__device__ __nv_bfloat16 g_Wr3[(size_t)NT_R3*18*64*64];

// ---------------- helpers ----------------
__device__ __forceinline__ uint32_t smem_u32(const void* p){
    uint32_t a;
    asm("{ .reg .u64 t; cvta.to.shared.u64 t, %1; cvt.u32.u64 %0, t; }" : "=r"(a) : "l"(p));
    return a;
}
__device__ __forceinline__ void cp16(uint32_t dst, const void* src){
    asm volatile("cp.async.cg.shared.global [%0], [%1], 16;" :: "r"(dst), "l"(src));
}
__device__ __forceinline__ void cp_commit(){
    asm volatile("cp.async.commit_group;" ::: "memory");
}
__device__ __forceinline__ void ldm4(uint32_t& r0, uint32_t& r1, uint32_t& r2, uint32_t& r3, uint32_t addr){
    asm volatile("ldmatrix.sync.aligned.m8n8.x4.shared.b16 {%0,%1,%2,%3}, [%4];"
                 : "=r"(r0), "=r"(r1), "=r"(r2), "=r"(r3) : "r"(addr));
}
__device__ __forceinline__ void mma16816(float* c, const uint32_t* a, uint32_t b0, uint32_t b1){
    asm volatile("mma.sync.aligned.m16n8k16.row.col.f32.bf16.bf16.f32 "
                 "{%0,%1,%2,%3}, {%4,%5,%6,%7}, {%8,%9}, {%0,%1,%2,%3};"
                 : "+f"(c[0]), "+f"(c[1]), "+f"(c[2]), "+f"(c[3])
                 : "r"(a[0]), "r"(a[1]), "r"(a[2]), "r"(a[3]), "r"(b0), "r"(b1));
}
__device__ __forceinline__ void write_split(__nv_bfloat16* row, int Kpad, int k, float x){
    __nv_bfloat16 h = __float2bfloat16(x);
    row[k] = h;
    row[Kpad + k] = __float2bfloat16(x - __bfloat162float(h));
}
__device__ __forceinline__ uint32_t sw128(uint32_t off){ return off ^ ((off >> 3) & 0x70); }

// ---------------- weight prepack: fp32 W[K,N] -> swizzled bf16 panels ----------------
// panel order g in [0,3P): g<P -> hi[g], P<=g<2P -> lo[g-P], g>=2P -> hi[g-2P]
// (matches A panels: hi, hi, lo -> products Ah*Wh + Ah*Wl + Al*Wh)
__global__ void prepack_w(const float* __restrict__ W, __nv_bfloat16* __restrict__ out,
                          int K, int N, int P, int ntiles)
{
    int idx = blockIdx.x * 256 + threadIdx.x;
    const int per_panel = 64 * 64;
    int total = ntiles * 3 * P * per_panel;
    if (idx >= total) return;
    int t   = idx / (3 * P * per_panel);
    int rem = idx - t * (3 * P * per_panel);
    int g   = rem / per_panel;
    int rp  = rem - g * per_panel;
    int r   = rp >> 6;          // n within tile
    int kk  = rp & 63;          // k within panel
    int pass = g / P;
    int k    = (g - pass * P) * 64 + kk;
    int n    = t * 64 + r;
    float w = (k < K && n < N) ? W[(size_t)k * N + n] : 0.f;
    __nv_bfloat16 v;
    if (pass == 1) { __nv_bfloat16 h = __float2bfloat16(w); v = __float2bfloat16(w - __bfloat162float(h)); }
    else           { v = __float2bfloat16(w); }
    uint32_t off = sw128((uint32_t)r * 128 + kk * 2);
    char* base = (char*)out + ((size_t)(t * 3 * P + g)) * 8192;
    *reinterpret_cast<__nv_bfloat16*>(base + off) = v;
}

// ---------------- warp-MMA GEMM (split-bf16, 3-pass K-concat) ----------------
// C[M,N] = act(A'[M,splitK] @ W' + bias + resid). M%128==0.
// A' row: [hi(Kpad) | lo(Kpad)] bf16, stride=2*Kpad.
// grid = (NT, M/128); 256 threads; BM=128, BN=64; warps 4m x 2n, warp tile 32x32.
__global__ void __launch_bounds__(256)
gemm_mma(const __nv_bfloat16* __restrict__ A, int astride, int P,
         const char* __restrict__ Wp,
         const float* __restrict__ bias, const float* __restrict__ resid,
         float* __restrict__ out, int N, int relu)
{
    extern __shared__ char smem[];
    const int tid  = threadIdx.x;
    const int wid  = tid >> 5;
    const int lane = tid & 31;
    const uint32_t sbase = smem_u32(smem);
    const uint32_t AOFF = 1024;
    const uint32_t WOFF = 1024 + 3 * 16384;
    const int PT = 3 * P;
    const size_t row0 = (size_t)blockIdx.y * 128;
    const int colbase = blockIdx.x * 64;

    auto issue_loads = [&](int g, int s){
        uint32_t abase = sbase + AOFF + s * 16384;
        int srcoff = ((g < 2 * P) ? (g % P) : (g - P)) * 64;   // elements
        #pragma unroll
        for (int i = 0; i < 4; i++) {
            int idx = tid + 256 * i;
            int r = idx >> 3, c = idx & 7;
            const char* src = (const char*)(A + (row0 + r) * (size_t)astride + srcoff) + c * 16;
            cp16(abase + sw128((uint32_t)r * 128 + c * 16), src);
        }
        const char* wsrc = Wp + ((size_t)(blockIdx.x * PT + g)) * 8192;
        uint32_t wbase = sbase + WOFF + s * 8192;
        #pragma unroll
        for (int j = 0; j < 2; j++) {
            int widx = tid + 256 * j;
            cp16(wbase + widx * 16, wsrc + (size_t)widx * 16);
        }
        cp_commit();
    };

    issue_loads(0, 0);
    if (PT > 1) issue_loads(1, 1);
    if (PT > 2) issue_loads(2, 2);

    const int mw = wid & 3;    // 0..3  (m block of 32)
    const int nw = wid >> 2;   // 0..1  (n block of 32)
    float acc[2][4][4];
    #pragma unroll
    for (int i = 0; i < 2; i++)
        #pragma unroll
        for (int j = 0; j < 4; j++)
            #pragma unroll
            for (int q = 0; q < 4; q++) acc[i][j][q] = 0.f;

    // ldmatrix lane address components
    const int q8 = lane >> 3;     // 0..3
    const int r8 = lane & 7;      // 0..7

    for (int g = 0; g < PT; g++) {
        int s = g % 3;
        int rem = PT - 1 - g;
        if (rem >= 2)      asm volatile("cp.async.wait_group 2;" ::: "memory");
        else if (rem == 1) asm volatile("cp.async.wait_group 1;" ::: "memory");
        else               asm volatile("cp.async.wait_group 0;" ::: "memory");
        __syncthreads();

        uint32_t abase = sbase + AOFF + s * 16384;
        uint32_t wbase = sbase + WOFF + s * 8192;

        #pragma unroll
        for (int ks = 0; ks < 4; ks++) {
            const int kbyte = ks * 32;  // 16 bf16
            // A fragments: 2 m-tiles of 16
            uint32_t a[2][4];
            #pragma unroll
            for (int tm = 0; tm < 2; tm++) {
                int arow = mw * 32 + tm * 16 + (q8 & 1) * 8 + r8;
                uint32_t off = sw128((uint32_t)arow * 128 + kbyte + (q8 >> 1) * 16);
                ldm4(a[tm][0], a[tm][1], a[tm][2], a[tm][3], abase + off);
            }
            // B fragments: 2 x ldmatrix.x4, each covering n16
            uint32_t b[2][4];
            #pragma unroll
            for (int tb = 0; tb < 2; tb++) {
                int nrow = nw * 32 + tb * 16 + (q8 >> 1) * 8 + r8;
                uint32_t off = sw128((uint32_t)nrow * 128 + kbyte + (q8 & 1) * 16);
                ldm4(b[tb][0], b[tb][1], b[tb][2], b[tb][3], wbase + off);
            }
            #pragma unroll
            for (int tm = 0; tm < 2; tm++)
                #pragma unroll
                for (int tn = 0; tn < 4; tn++)
                    mma16816(acc[tm][tn], a[tm], b[tn >> 1][(tn & 1) * 2],
                             b[tn >> 1][(tn & 1) * 2 + 1]);
        }

        if (g + 3 < PT) {
            __syncthreads();
            issue_loads(g + 3, s);
        }
    }

    // epilogue: acc[tm][tn][q] -> (m, n)
    // m = row0 + mw*32 + tm*16 + (lane>>2) + (q>=2 ? 8 : 0)
    // n = colbase + nw*32 + tn*8 + (lane&3)*2 + (q&1)
    #pragma unroll
    for (int tm = 0; tm < 2; tm++) {
        #pragma unroll
        for (int half = 0; half < 2; half++) {
            size_t r = row0 + mw * 32 + tm * 16 + (lane >> 2) + half * 8;
            #pragma unroll
            for (int tn = 0; tn < 4; tn++) {
                int c = colbase + nw * 32 + tn * 8 + (lane & 3) * 2;
                float v0 = acc[tm][tn][half * 2];
                float v1 = acc[tm][tn][half * 2 + 1];
                if (c < N) {
                    v0 += bias[c];
                    if (resid) v0 += resid[r * N + c];
                    if (relu) v0 = fmaxf(v0, 0.f);
                    out[r * N + c] = v0;
                }
                if (c + 1 < N) {
                    v1 += bias[c + 1];
                    if (resid) v1 += resid[r * N + c + 1];
                    if (relu) v1 = fmaxf(v1, 0.f);
                    out[r * N + c + 1] = v1;
                }
            }
        }
    }
}

// ---------------- A' builders ----------------
__global__ void conv_h0(const float* __restrict__ v, const float* __restrict__ e,
                        const int* __restrict__ src, __nv_bfloat16* __restrict__ A)
{
    size_t idx = (size_t)blockIdx.x * 256 + threadIdx.x;
    if (idx >= (size_t)EEDGE * KP_H0) return;
    int r = (int)(idx / KP_H0), k = (int)(idx % KP_H0);
    float x = 0.f;
    if (k < NF)            x = v[(size_t)src[r] * (NF + 1) + k];
    else if (k < NF + EFE) x = e[(size_t)r * (EFE + 1) + (k - NF)];
    write_split(A + (size_t)r * 2 * KP_H0, KP_H0, k, x);
}

__global__ void conv_hv(const float* __restrict__ v, const float* __restrict__ mv,
                        __nv_bfloat16* __restrict__ A)
{
    size_t idx = (size_t)blockIdx.x * 256 + threadIdx.x;
    if (idx >= (size_t)NNODE * KP_HV) return;
    int r = (int)(idx / KP_HV), k = (int)(idx % KP_HV);
    float x = 0.f;
    if (k < NF)           x = v[(size_t)r * (NF + 1) + k];
    else if (k < NF + HH) x = mv[(size_t)r * HH + (k - NF)];
    write_split(A + (size_t)r * 2 * KP_HV, KP_HV, k, x);
}

__global__ void conv_plain(const float* __restrict__ X, int Nin, int Kpad, int M,
                           __nv_bfloat16* __restrict__ A)
{
    size_t idx = (size_t)blockIdx.x * 256 + threadIdx.x;
    if (idx >= (size_t)M * Kpad) return;
    int r = (int)(idx / Kpad), k = (int)(idx % Kpad);
    float x = (k < Nin) ? X[(size_t)r * Nin + k] : 0.f;
    write_split(A + (size_t)r * 2 * Kpad, Kpad, k, x);
}

// mean over 32 nodes + concat globals -> A'_r1
__global__ void __launch_bounds__(256)
mean_conv(const float* __restrict__ hv, const float* __restrict__ gl,
          __nv_bfloat16* __restrict__ A)
{
    const int b = blockIdx.x;
    __nv_bfloat16* row = A + (size_t)b * 2 * KP_R1;
    for (int k = threadIdx.x; k < KP_R1; k += 256) {
        float x = 0.f;
        if (k < HH) {
            float s = 0.f;
            #pragma unroll 8
            for (int i = 0; i < NPER; i++) s += hv[(size_t)(b * NPER + i) * HH + k];
            x = s * (1.0f / NPER);
        } else if (k < HH + GG) {
            x = gl[(size_t)b * GG + (k - HH)];
        }
        write_split(row, KP_R1, k, x);
    }
}

// ---------------- per-graph message kernels ----------------
#define MSG_CH 100
__global__ void __launch_bounds__(256)
msg_kernel(const float* __restrict__ h, const int* __restrict__ src,
           const int* __restrict__ dst, __nv_bfloat16* __restrict__ A)
{
    __shared__ int s_src[64], s_dst[64];
    __shared__ float h_s[64 * MSG_CH];
    __shared__ float acc_s[32 * MSG_CH];
    const int b = blockIdx.x, tid = threadIdx.x;
    if (tid < 64) {
        s_src[tid] = src[b * 64 + tid] - b * 32;
        s_dst[tid] = dst[b * 64 + tid] - b * 32;
    }
    for (int c0 = 0; c0 < HH; c0 += MSG_CH) {
        __syncthreads();
        for (int idx = tid; idx < 64 * MSG_CH; idx += 256) {
            int e = idx / MSG_CH, c = idx - e * MSG_CH;
            h_s[idx] = h[(size_t)(b * 64 + e) * HH + c0 + c];
        }
        for (int idx = tid; idx < 32 * MSG_CH; idx += 256) acc_s[idx] = 0.f;
        __syncthreads();
        for (int idx = tid; idx < 64 * MSG_CH; idx += 256) {
            int e = idx / MSG_CH, c = idx - e * MSG_CH;
            atomicAdd(&acc_s[s_dst[e] * MSG_CH + c], h_s[idx]);
        }
        __syncthreads();
        for (int idx = tid; idx < 64 * MSG_CH; idx += 256) {
            int e = idx / MSG_CH, c = idx - e * MSG_CH;
            float x = acc_s[s_src[e] * MSG_CH + c] - h_s[(e ^ 1) * MSG_CH + c];
            write_split(A + (size_t)(b * 64 + e) * 2 * KP_L, KP_L, c0 + c, x);
        }
    }
    for (int idx = tid; idx < 64 * (KP_L - HH); idx += 256) {
        int e = idx / (KP_L - HH), k = HH + idx % (KP_L - HH);
        __nv_bfloat16* row = A + (size_t)(b * 64 + e) * 2 * KP_L;
        row[k] = __float2bfloat16(0.f);
        row[KP_L + k] = __float2bfloat16(0.f);
    }
}

__global__ void __launch_bounds__(256)
mv_kernel(const float* __restrict__ h, const int* __restrict__ src,
          float* __restrict__ mv)
{
    __shared__ int s_src[64];
    __shared__ float h_s[64 * MSG_CH];
    __shared__ float acc_s[32 * MSG_CH];
    const int b = blockIdx.x, tid = threadIdx.x;
    if (tid < 64) s_src[tid] = src[b * 64 + tid] - b * 32;
    for (int c0 = 0; c0 < HH; c0 += MSG_CH) {
        __syncthreads();
        for (int idx = tid; idx < 64 * MSG_CH; idx += 256) {
            int e = idx / MSG_CH, c = idx - e * MSG_CH;
            h_s[idx] = h[(size_t)(b * 64 + e) * HH + c0 + c];
        }
        for (int idx = tid; idx < 32 * MSG_CH; idx += 256) acc_s[idx] = 0.f;
        __syncthreads();
        for (int idx = tid; idx < 64 * MSG_CH; idx += 256) {
            int e = idx / MSG_CH, c = idx - e * MSG_CH;
            atomicAdd(&acc_s[s_src[e] * MSG_CH + c], h_s[idx]);
        }
        __syncthreads();
        for (int idx = tid; idx < 32 * MSG_CH; idx += 256) {
            int n = idx / MSG_CH, c = idx - n * MSG_CH;
            mv[(size_t)(b * 32 + n) * HH + c0 + c] = acc_s[idx];
        }
    }
}

// ---------------- launch ----------------
#define GEMM_SMEM (1024 + 3*16384 + 3*8192)

extern "C" void kernel_launch(void* const* d_in, const int* in_sizes, int n_in,
                              void* d_out, int out_size)
{
    (void)in_sizes; (void)n_in; (void)out_size;
    const float* v   = (const float*)d_in[0];
    const float* e   = (const float*)d_in[1];
    const float* gl  = (const float*)d_in[2];
    const float* Wi  = (const float*)d_in[3];
    const float* bi  = (const float*)d_in[4];
    const float* Wm  = (const float*)d_in[5];
    const float* bm  = (const float*)d_in[6];
    const float* Wa  = (const float*)d_in[7];
    const float* ba  = (const float*)d_in[8];
    const float* Wr1 = (const float*)d_in[9];
    const float* br1 = (const float*)d_in[10];
    const float* Wr2 = (const float*)d_in[11];
    const float* br2 = (const float*)d_in[12];
    const float* Wr3 = (const float*)d_in[13];
    const float* br3 = (const float*)d_in[14];
    const int*   src = (const int*)d_in[15];
    const int*   dst = (const int*)d_in[16];
    float* out = (float*)d_out;

    float *h0, *hA, *hB, *mv, *hv, *r1, *r2;
    __nv_bfloat16 *Ae, *Ahv, *Ar1, *Ar2, *Ar3, *Wip, *Wmp, *Wap, *Wr1p, *Wr2p, *Wr3p;
    cudaGetSymbolAddress((void**)&h0, g_h0);
    cudaGetSymbolAddress((void**)&hA, g_hA);
    cudaGetSymbolAddress((void**)&hB, g_hB);
    cudaGetSymbolAddress((void**)&mv, g_mv);
    cudaGetSymbolAddress((void**)&hv, g_hv);
    cudaGetSymbolAddress((void**)&r1, g_r1);
    cudaGetSymbolAddress((void**)&r2, g_r2);
    cudaGetSymbolAddress((void**)&Ae,  g_Ae);
    cudaGetSymbolAddress((void**)&Ahv, g_Ahv);
    cudaGetSymbolAddress((void**)&Ar1, g_Ar1);
    cudaGetSymbolAddress((void**)&Ar2, g_Ar2);
    cudaGetSymbolAddress((void**)&Ar3, g_Ar3);
    cudaGetSymbolAddress((void**)&Wip, g_Wi);
    cudaGetSymbolAddress((void**)&Wmp, g_Wm);
    cudaGetSymbolAddress((void**)&Wap, g_Wa);
    cudaGetSymbolAddress((void**)&Wr1p, g_Wr1);
    cudaGetSymbolAddress((void**)&Wr2p, g_Wr2);
    cudaGetSymbolAddress((void**)&Wr3p, g_Wr3);

    cudaFuncSetAttribute(gemm_mma, cudaFuncAttributeMaxDynamicSharedMemorySize, GEMM_SMEM);

    // ---- weight prepacks ----
    auto pk = [&](const float* W, __nv_bfloat16* o, int K, int N, int P, int nt){
        int total = nt * 3 * P * 64 * 64;
        prepack_w<<<(total + 255) / 256, 256>>>(W, o, K, N, P, nt);
    };
    pk(Wi,  Wip,  NF + EFE, HH,  3, NT_H);
    pk(Wm,  Wmp,  HH,       HH,  5, NT_H);
    pk(Wa,  Wap,  NF + HH,  HH,  7, NT_H);
    pk(Wr1, Wr1p, HH + GG,  RR1, 8, NT_R1);
    pk(Wr2, Wr2p, RR1,      RR2, 9, NT_R2);
    pk(Wr3, Wr3p, RR2,      TT,  6, NT_R3);

    // ---- 1) h0 = relu([vv[src]|ee] @ Wi + bi) ----
    conv_h0<<<(int)(((size_t)EEDGE * KP_H0 + 255) / 256), 256>>>(v, e, src, Ae);
    gemm_mma<<<dim3(NT_H, EEDGE / 128), 256, GEMM_SMEM>>>(
        Ae, 2 * KP_H0, 3, (const char*)Wip, bi, nullptr, h0, HH, 1);

    // ---- 2) message-passing layers ----
    const float* hin = h0;
    float* houts[3] = {hA, hB, hA};
    for (int l = 0; l < 3; l++) {
        msg_kernel<<<BB, 256>>>(hin, src, dst, Ae);
        gemm_mma<<<dim3(NT_H, EEDGE / 128), 256, GEMM_SMEM>>>(
            Ae, 2 * KP_L, 5, (const char*)Wmp, bm, h0, houts[l], HH, 1);
        hin = houts[l];
    }

    // ---- 3) node aggregation + node MLP ----
    mv_kernel<<<BB, 256>>>(hin, src, mv);
    conv_hv<<<(int)(((size_t)NNODE * KP_HV + 255) / 256), 256>>>(v, mv, Ahv);
    gemm_mma<<<dim3(NT_H, NNODE / 128), 256, GEMM_SMEM>>>(
        Ahv, 2 * KP_HV, 7, (const char*)Wap, ba, nullptr, hv, HH, 1);

    // ---- 4) graph mean + globals concat ----
    mean_conv<<<BB, 256>>>(hv, gl, Ar1);

    // ---- 5) readout MLP ----
    gemm_mma<<<dim3(NT_R1, BB / 128), 256, GEMM_SMEM>>>(
        Ar1, 2 * KP_R1, 8, (const char*)Wr1p, br1, nullptr, r1, RR1, 1);
    conv_plain<<<(int)(((size_t)BB * KP_R2 + 255) / 256), 256>>>(r1, RR1, KP_R2, BB, Ar2);
    gemm_mma<<<dim3(NT_R2, BB / 128), 256, GEMM_SMEM>>>(
        Ar2, 2 * KP_R2, 9, (const char*)Wr2p, br2, nullptr, r2, RR2, 1);
    conv_plain<<<(int)(((size_t)BB * KP_R3 + 255) / 256), 256>>>(r2, RR2, KP_R3, BB, Ar3);
    gemm_mma<<<dim3(NT_R3, BB / 128), 256, GEMM_SMEM>>>(
        Ar3, 2 * KP_R3, 6, (const char*)Wr3p, br3, nullptr, out, TT, 0);
}

// round 7
// speedup vs baseline: 2.5992x; 1.0388x over previous
#include <cuda_runtime.h>
#include <cuda_bf16.h>
#include <cstdint>

// ---------------- problem constants ----------------
#define NF   133
#define EFE  14
#define HH   300
#define GG   200
#define TT   12
#define BB   4096
#define NPER 32
#define NNODE (BB*NPER)      // 131072
#define EEDGE (BB*64)        // 262144
#define RR1  550
#define RR2  378

// padded K per GEMM (multiple of 64); P = K-panels of 64
#define KP_H0 192   // K=147, P=3
#define KP_L  320   // K=300, P=5
#define KP_HV 448   // K=433, P=7
#define KP_R1 512   // K=500, P=8
#define KP_R2 576   // K=550, P=9
#define KP_R3 384   // K=378, P=6

// N-tile width (per CTA) is fixed at 64.
#define NT_H  5     // ceil(300/64) -> 320
#define NT_R1 9     // 576
#define NT_R2 6     // 384
#define NT_R3 1     // 64

// ---------------- scratch ----------------
__device__ float g_h0[(size_t)EEDGE*HH];
__device__ float g_hA[(size_t)EEDGE*HH];
__device__ float g_hB[(size_t)EEDGE*HH];
__device__ float g_mv[(size_t)NNODE*HH];
__device__ float g_hv[(size_t)NNODE*HH];
__device__ float g_r1[(size_t)BB*RR1];
__device__ float g_r2[(size_t)BB*RR2];

__device__ __nv_bfloat16 g_Ae [(size_t)EEDGE*2*KP_L];
__device__ __nv_bfloat16 g_Ahv[(size_t)NNODE*2*KP_HV];
__device__ __nv_bfloat16 g_Ar1[(size_t)BB*2*KP_R1];
__device__ __nv_bfloat16 g_Ar2[(size_t)BB*2*KP_R2];
__device__ __nv_bfloat16 g_Ar3[(size_t)BB*2*KP_R3];

// W panels: [ntile][3P][64 rows x 128B] swizzled bf16
__device__ __nv_bfloat16 g_Wi [(size_t)NT_H *9 *64*64];
__device__ __nv_bfloat16 g_Wm [(size_t)NT_H *15*64*64];
__device__ __nv_bfloat16 g_Wa [(size_t)NT_H *21*64*64];
__device__ __nv_bfloat16 g_Wr1[(size_t)NT_R1*24*64*64];
__device__ __nv_bfloat16 g_Wr2[(size_t)NT_R2*27*64*64];
__device__ __nv_bfloat16 g_Wr3[(size_t)NT_R3*18*64*64];

// ---------------- helpers ----------------
__device__ __forceinline__ uint32_t smem_u32(const void* p){
    uint32_t a;
    asm("{ .reg .u64 t; cvta.to.shared.u64 t, %1; cvt.u32.u64 %0, t; }" : "=r"(a) : "l"(p));
    return a;
}
__device__ __forceinline__ void cp16(uint32_t dst, const void* src){
    asm volatile("cp.async.cg.shared.global [%0], [%1], 16;" :: "r"(dst), "l"(src));
}
__device__ __forceinline__ void cp_commit(){
    asm volatile("cp.async.commit_group;" ::: "memory");
}
__device__ __forceinline__ void ldm4(uint32_t& r0, uint32_t& r1, uint32_t& r2, uint32_t& r3, uint32_t addr){
    asm volatile("ldmatrix.sync.aligned.m8n8.x4.shared.b16 {%0,%1,%2,%3}, [%4];"
                 : "=r"(r0), "=r"(r1), "=r"(r2), "=r"(r3) : "r"(addr));
}
__device__ __forceinline__ void mma16816(float* c, const uint32_t* a, uint32_t b0, uint32_t b1){
    asm volatile("mma.sync.aligned.m16n8k16.row.col.f32.bf16.bf16.f32 "
                 "{%0,%1,%2,%3}, {%4,%5,%6,%7}, {%8,%9}, {%0,%1,%2,%3};"
                 : "+f"(c[0]), "+f"(c[1]), "+f"(c[2]), "+f"(c[3])
                 : "r"(a[0]), "r"(a[1]), "r"(a[2]), "r"(a[3]), "r"(b0), "r"(b1));
}
__device__ __forceinline__ void write_split(__nv_bfloat16* row, int Kpad, int k, float x){
    __nv_bfloat16 h = __float2bfloat16(x);
    row[k] = h;
    row[Kpad + k] = __float2bfloat16(x - __bfloat162float(h));
}
__device__ __forceinline__ uint32_t sw128(uint32_t off){ return off ^ ((off >> 3) & 0x70); }

// ---------------- weight prepack: fp32 W[K,N] -> swizzled bf16 panels ----------------
// panel order g in [0,3P): g<P -> hi[g], P<=g<2P -> lo[g-P], g>=2P -> hi[g-2P]
// (matches A panels: hi, hi, lo -> products Ah*Wh + Ah*Wl + Al*Wh)
__global__ void prepack_w(const float* __restrict__ W, __nv_bfloat16* __restrict__ out,
                          int K, int N, int P, int ntiles)
{
    int idx = blockIdx.x * 256 + threadIdx.x;
    const int per_panel = 64 * 64;
    int total = ntiles * 3 * P * per_panel;
    if (idx >= total) return;
    int t   = idx / (3 * P * per_panel);
    int rem = idx - t * (3 * P * per_panel);
    int g   = rem / per_panel;
    int rp  = rem - g * per_panel;
    int r   = rp >> 6;          // n within tile
    int kk  = rp & 63;          // k within panel
    int pass = g / P;
    int k    = (g - pass * P) * 64 + kk;
    int n    = t * 64 + r;
    float w = (k < K && n < N) ? W[(size_t)k * N + n] : 0.f;
    __nv_bfloat16 v;
    if (pass == 1) { __nv_bfloat16 h = __float2bfloat16(w); v = __float2bfloat16(w - __bfloat162float(h)); }
    else           { v = __float2bfloat16(w); }
    uint32_t off = sw128((uint32_t)r * 128 + kk * 2);
    char* base = (char*)out + ((size_t)(t * 3 * P + g)) * 8192;
    *reinterpret_cast<__nv_bfloat16*>(base + off) = v;
}

// ---------------- warp-MMA GEMM (split-bf16, 3-pass K-concat) ----------------
// C[M,N] = act(A'[M,splitK] @ W' + bias + resid). M%128==0.
// A' row: [hi(Kpad) | lo(Kpad)] bf16, stride=2*Kpad.
// grid = (NT, M/128); 256 threads; BM=128, BN=64; warps 4m x 2n, warp tile 32x32.
// 4-stage cp.async ring, ONE __syncthreads per panel (issue g+3 targets the
// stage consumed at iteration g-1, made safe by this iteration's barrier).
#define NSTAGE 4
#define A_STAGE_BYTES 16384
#define W_STAGE_BYTES 8192
#define AOFF 1024
#define WOFF (1024 + NSTAGE * A_STAGE_BYTES)
#define GEMM_SMEM (WOFF + NSTAGE * W_STAGE_BYTES)

__global__ void __launch_bounds__(256, 2)
gemm_mma(const __nv_bfloat16* __restrict__ A, int astride, int P,
         const char* __restrict__ Wp,
         const float* __restrict__ bias, const float* __restrict__ resid,
         float* __restrict__ out, int N, int relu)
{
    extern __shared__ char smem[];
    const int tid  = threadIdx.x;
    const int wid  = tid >> 5;
    const int lane = tid & 31;
    const uint32_t sbase = smem_u32(smem);
    const int PT = 3 * P;
    const size_t row0 = (size_t)blockIdx.y * 128;
    const int colbase = blockIdx.x * 64;

    auto issue_loads = [&](int g){
        int s = g & (NSTAGE - 1);
        uint32_t abase = sbase + AOFF + s * A_STAGE_BYTES;
        int srcoff = ((g < 2 * P) ? (g % P) : (g - P)) * 64;   // elements
        #pragma unroll
        for (int i = 0; i < 4; i++) {
            int idx = tid + 256 * i;
            int r = idx >> 3, c = idx & 7;
            const char* src = (const char*)(A + (row0 + r) * (size_t)astride + srcoff) + c * 16;
            cp16(abase + sw128((uint32_t)r * 128 + c * 16), src);
        }
        const char* wsrc = Wp + ((size_t)(blockIdx.x * PT + g)) * 8192;
        uint32_t wbase = sbase + WOFF + s * W_STAGE_BYTES;
        #pragma unroll
        for (int j = 0; j < 2; j++) {
            int widx = tid + 256 * j;
            cp16(wbase + widx * 16, wsrc + (size_t)widx * 16);
        }
        cp_commit();
    };

    issue_loads(0); issue_loads(1); issue_loads(2);

    const int mw = wid & 3;    // m block of 32
    const int nw = wid >> 2;   // n block of 32
    float acc[2][4][4];
    #pragma unroll
    for (int i = 0; i < 2; i++)
        #pragma unroll
        for (int j = 0; j < 4; j++)
            #pragma unroll
            for (int q = 0; q < 4; q++) acc[i][j][q] = 0.f;

    const int q8 = lane >> 3;     // 0..3
    const int r8 = lane & 7;      // 0..7

    for (int g = 0; g < PT; g++) {
        int s = g & (NSTAGE - 1);
        int rem = PT - 1 - g;
        if (rem >= 2)      asm volatile("cp.async.wait_group 2;" ::: "memory");
        else if (rem == 1) asm volatile("cp.async.wait_group 1;" ::: "memory");
        else               asm volatile("cp.async.wait_group 0;" ::: "memory");
        __syncthreads();

        // issue next panel into the stage freed at iteration g-1
        if (g + 3 < PT) issue_loads(g + 3);

        uint32_t abase = sbase + AOFF + s * A_STAGE_BYTES;
        uint32_t wbase = sbase + WOFF + s * W_STAGE_BYTES;

        #pragma unroll
        for (int ks = 0; ks < 4; ks++) {
            const int kbyte = ks * 32;  // 16 bf16
            uint32_t a[2][4];
            #pragma unroll
            for (int tm = 0; tm < 2; tm++) {
                int arow = mw * 32 + tm * 16 + (q8 & 1) * 8 + r8;
                uint32_t off = sw128((uint32_t)arow * 128 + kbyte + (q8 >> 1) * 16);
                ldm4(a[tm][0], a[tm][1], a[tm][2], a[tm][3], abase + off);
            }
            uint32_t b[2][4];
            #pragma unroll
            for (int tb = 0; tb < 2; tb++) {
                int nrow = nw * 32 + tb * 16 + (q8 >> 1) * 8 + r8;
                uint32_t off = sw128((uint32_t)nrow * 128 + kbyte + (q8 & 1) * 16);
                ldm4(b[tb][0], b[tb][1], b[tb][2], b[tb][3], wbase + off);
            }
            #pragma unroll
            for (int tm = 0; tm < 2; tm++)
                #pragma unroll
                for (int tn = 0; tn < 4; tn++)
                    mma16816(acc[tm][tn], a[tm], b[tn >> 1][(tn & 1) * 2],
                             b[tn >> 1][(tn & 1) * 2 + 1]);
        }
    }

    // epilogue: acc[tm][tn][q] -> (m, n); (c, c+1) pairs are contiguous, N is
    // always even here and c is even -> 8B-aligned float2 traffic throughout.
    #pragma unroll
    for (int tm = 0; tm < 2; tm++) {
        #pragma unroll
        for (int half = 0; half < 2; half++) {
            size_t r = row0 + mw * 32 + tm * 16 + (lane >> 2) + half * 8;
            #pragma unroll
            for (int tn = 0; tn < 4; tn++) {
                int c = colbase + nw * 32 + tn * 8 + (lane & 3) * 2;
                if (c < N) {
                    float2 bv = *reinterpret_cast<const float2*>(&bias[c]);
                    float v0 = acc[tm][tn][half * 2]     + bv.x;
                    float v1 = acc[tm][tn][half * 2 + 1] + bv.y;
                    if (resid) {
                        float2 rv = *reinterpret_cast<const float2*>(&resid[r * N + c]);
                        v0 += rv.x; v1 += rv.y;
                    }
                    if (relu) { v0 = fmaxf(v0, 0.f); v1 = fmaxf(v1, 0.f); }
                    float2 q; q.x = v0; q.y = v1;
                    *reinterpret_cast<float2*>(&out[r * N + c]) = q;
                }
            }
        }
    }
}

// ---------------- A' builders ----------------
__global__ void conv_h0(const float* __restrict__ v, const float* __restrict__ e,
                        const int* __restrict__ src, __nv_bfloat16* __restrict__ A)
{
    size_t idx = (size_t)blockIdx.x * 256 + threadIdx.x;
    if (idx >= (size_t)EEDGE * KP_H0) return;
    int r = (int)(idx / KP_H0), k = (int)(idx % KP_H0);
    float x = 0.f;
    if (k < NF)            x = v[(size_t)src[r] * (NF + 1) + k];
    else if (k < NF + EFE) x = e[(size_t)r * (EFE + 1) + (k - NF)];
    write_split(A + (size_t)r * 2 * KP_H0, KP_H0, k, x);
}

__global__ void conv_hv(const float* __restrict__ v, const float* __restrict__ mv,
                        __nv_bfloat16* __restrict__ A)
{
    size_t idx = (size_t)blockIdx.x * 256 + threadIdx.x;
    if (idx >= (size_t)NNODE * KP_HV) return;
    int r = (int)(idx / KP_HV), k = (int)(idx % KP_HV);
    float x = 0.f;
    if (k < NF)           x = v[(size_t)r * (NF + 1) + k];
    else if (k < NF + HH) x = mv[(size_t)r * HH + (k - NF)];
    write_split(A + (size_t)r * 2 * KP_HV, KP_HV, k, x);
}

__global__ void conv_plain(const float* __restrict__ X, int Nin, int Kpad, int M,
                           __nv_bfloat16* __restrict__ A)
{
    size_t idx = (size_t)blockIdx.x * 256 + threadIdx.x;
    if (idx >= (size_t)M * Kpad) return;
    int r = (int)(idx / Kpad), k = (int)(idx % Kpad);
    float x = (k < Nin) ? X[(size_t)r * Nin + k] : 0.f;
    write_split(A + (size_t)r * 2 * Kpad, Kpad, k, x);
}

// mean over 32 nodes + concat globals -> A'_r1
__global__ void __launch_bounds__(256)
mean_conv(const float* __restrict__ hv, const float* __restrict__ gl,
          __nv_bfloat16* __restrict__ A)
{
    const int b = blockIdx.x;
    __nv_bfloat16* row = A + (size_t)b * 2 * KP_R1;
    for (int k = threadIdx.x; k < KP_R1; k += 256) {
        float x = 0.f;
        if (k < HH) {
            float s = 0.f;
            #pragma unroll 8
            for (int i = 0; i < NPER; i++) s += hv[(size_t)(b * NPER + i) * HH + k];
            x = s * (1.0f / NPER);
        } else if (k < HH + GG) {
            x = gl[(size_t)b * GG + (k - HH)];
        }
        write_split(row, KP_R1, k, x);
    }
}

// ---------------- per-graph message kernels ----------------
#define MSG_CH 100
__global__ void __launch_bounds__(256)
msg_kernel(const float* __restrict__ h, const int* __restrict__ src,
           const int* __restrict__ dst, __nv_bfloat16* __restrict__ A)
{
    __shared__ int s_src[64], s_dst[64];
    __shared__ float h_s[64 * MSG_CH];
    __shared__ float acc_s[32 * MSG_CH];
    const int b = blockIdx.x, tid = threadIdx.x;
    if (tid < 64) {
        s_src[tid] = src[b * 64 + tid] - b * 32;
        s_dst[tid] = dst[b * 64 + tid] - b * 32;
    }
    for (int c0 = 0; c0 < HH; c0 += MSG_CH) {
        __syncthreads();
        for (int idx = tid; idx < 64 * MSG_CH; idx += 256) {
            int e = idx / MSG_CH, c = idx - e * MSG_CH;
            h_s[idx] = h[(size_t)(b * 64 + e) * HH + c0 + c];
        }
        for (int idx = tid; idx < 32 * MSG_CH; idx += 256) acc_s[idx] = 0.f;
        __syncthreads();
        for (int idx = tid; idx < 64 * MSG_CH; idx += 256) {
            int e = idx / MSG_CH, c = idx - e * MSG_CH;
            atomicAdd(&acc_s[s_dst[e] * MSG_CH + c], h_s[idx]);
        }
        __syncthreads();
        for (int idx = tid; idx < 64 * MSG_CH; idx += 256) {
            int e = idx / MSG_CH, c = idx - e * MSG_CH;
            float x = acc_s[s_src[e] * MSG_CH + c] - h_s[(e ^ 1) * MSG_CH + c];
            write_split(A + (size_t)(b * 64 + e) * 2 * KP_L, KP_L, c0 + c, x);
        }
    }
    for (int idx = tid; idx < 64 * (KP_L - HH); idx += 256) {
        int e = idx / (KP_L - HH), k = HH + idx % (KP_L - HH);
        __nv_bfloat16* row = A + (size_t)(b * 64 + e) * 2 * KP_L;
        row[k] = __float2bfloat16(0.f);
        row[KP_L + k] = __float2bfloat16(0.f);
    }
}

__global__ void __launch_bounds__(256)
mv_kernel(const float* __restrict__ h, const int* __restrict__ src,
          float* __restrict__ mv)
{
    __shared__ int s_src[64];
    __shared__ float h_s[64 * MSG_CH];
    __shared__ float acc_s[32 * MSG_CH];
    const int b = blockIdx.x, tid = threadIdx.x;
    if (tid < 64) s_src[tid] = src[b * 64 + tid] - b * 32;
    for (int c0 = 0; c0 < HH; c0 += MSG_CH) {
        __syncthreads();
        for (int idx = tid; idx < 64 * MSG_CH; idx += 256) {
            int e = idx / MSG_CH, c = idx - e * MSG_CH;
            h_s[idx] = h[(size_t)(b * 64 + e) * HH + c0 + c];
        }
        for (int idx = tid; idx < 32 * MSG_CH; idx += 256) acc_s[idx] = 0.f;
        __syncthreads();
        for (int idx = tid; idx < 64 * MSG_CH; idx += 256) {
            int e = idx / MSG_CH, c = idx - e * MSG_CH;
            atomicAdd(&acc_s[s_src[e] * MSG_CH + c], h_s[idx]);
        }
        __syncthreads();
        for (int idx = tid; idx < 32 * MSG_CH; idx += 256) {
            int n = idx / MSG_CH, c = idx - n * MSG_CH;
            mv[(size_t)(b * 32 + n) * HH + c0 + c] = acc_s[idx];
        }
    }
}

// ---------------- launch ----------------
extern "C" void kernel_launch(void* const* d_in, const int* in_sizes, int n_in,
                              void* d_out, int out_size)
{
    (void)in_sizes; (void)n_in; (void)out_size;
    const float* v   = (const float*)d_in[0];
    const float* e   = (const float*)d_in[1];
    const float* gl  = (const float*)d_in[2];
    const float* Wi  = (const float*)d_in[3];
    const float* bi  = (const float*)d_in[4];
    const float* Wm  = (const float*)d_in[5];
    const float* bm  = (const float*)d_in[6];
    const float* Wa  = (const float*)d_in[7];
    const float* ba  = (const float*)d_in[8];
    const float* Wr1 = (const float*)d_in[9];
    const float* br1 = (const float*)d_in[10];
    const float* Wr2 = (const float*)d_in[11];
    const float* br2 = (const float*)d_in[12];
    const float* Wr3 = (const float*)d_in[13];
    const float* br3 = (const float*)d_in[14];
    const int*   src = (const int*)d_in[15];
    const int*   dst = (const int*)d_in[16];
    float* out = (float*)d_out;

    float *h0, *hA, *hB, *mv, *hv, *r1, *r2;
    __nv_bfloat16 *Ae, *Ahv, *Ar1, *Ar2, *Ar3, *Wip, *Wmp, *Wap, *Wr1p, *Wr2p, *Wr3p;
    cudaGetSymbolAddress((void**)&h0, g_h0);
    cudaGetSymbolAddress((void**)&hA, g_hA);
    cudaGetSymbolAddress((void**)&hB, g_hB);
    cudaGetSymbolAddress((void**)&mv, g_mv);
    cudaGetSymbolAddress((void**)&hv, g_hv);
    cudaGetSymbolAddress((void**)&r1, g_r1);
    cudaGetSymbolAddress((void**)&r2, g_r2);
    cudaGetSymbolAddress((void**)&Ae,  g_Ae);
    cudaGetSymbolAddress((void**)&Ahv, g_Ahv);
    cudaGetSymbolAddress((void**)&Ar1, g_Ar1);
    cudaGetSymbolAddress((void**)&Ar2, g_Ar2);
    cudaGetSymbolAddress((void**)&Ar3, g_Ar3);
    cudaGetSymbolAddress((void**)&Wip, g_Wi);
    cudaGetSymbolAddress((void**)&Wmp, g_Wm);
    cudaGetSymbolAddress((void**)&Wap, g_Wa);
    cudaGetSymbolAddress((void**)&Wr1p, g_Wr1);
    cudaGetSymbolAddress((void**)&Wr2p, g_Wr2);
    cudaGetSymbolAddress((void**)&Wr3p, g_Wr3);

    cudaFuncSetAttribute(gemm_mma, cudaFuncAttributeMaxDynamicSharedMemorySize, GEMM_SMEM);

    // ---- weight prepacks ----
    auto pk = [&](const float* W, __nv_bfloat16* o, int K, int N, int P, int nt){
        int total = nt * 3 * P * 64 * 64;
        prepack_w<<<(total + 255) / 256, 256>>>(W, o, K, N, P, nt);
    };
    pk(Wi,  Wip,  NF + EFE, HH,  3, NT_H);
    pk(Wm,  Wmp,  HH,       HH,  5, NT_H);
    pk(Wa,  Wap,  NF + HH,  HH,  7, NT_H);
    pk(Wr1, Wr1p, HH + GG,  RR1, 8, NT_R1);
    pk(Wr2, Wr2p, RR1,      RR2, 9, NT_R2);
    pk(Wr3, Wr3p, RR2,      TT,  6, NT_R3);

    // ---- 1) h0 = relu([vv[src]|ee] @ Wi + bi) ----
    conv_h0<<<(int)(((size_t)EEDGE * KP_H0 + 255) / 256), 256>>>(v, e, src, Ae);
    gemm_mma<<<dim3(NT_H, EEDGE / 128), 256, GEMM_SMEM>>>(
        Ae, 2 * KP_H0, 3, (const char*)Wip, bi, nullptr, h0, HH, 1);

    // ---- 2) message-passing layers ----
    const float* hin = h0;
    float* houts[3] = {hA, hB, hA};
    for (int l = 0; l < 3; l++) {
        msg_kernel<<<BB, 256>>>(hin, src, dst, Ae);
        gemm_mma<<<dim3(NT_H, EEDGE / 128), 256, GEMM_SMEM>>>(
            Ae, 2 * KP_L, 5, (const char*)Wmp, bm, h0, houts[l], HH, 1);
        hin = houts[l];
    }

    // ---- 3) node aggregation + node MLP ----
    mv_kernel<<<BB, 256>>>(hin, src, mv);
    conv_hv<<<(int)(((size_t)NNODE * KP_HV + 255) / 256), 256>>>(v, mv, Ahv);
    gemm_mma<<<dim3(NT_H, NNODE / 128), 256, GEMM_SMEM>>>(
        Ahv, 2 * KP_HV, 7, (const char*)Wap, ba, nullptr, hv, HH, 1);

    // ---- 4) graph mean + globals concat ----
    mean_conv<<<BB, 256>>>(hv, gl, Ar1);

    // ---- 5) readout MLP ----
    gemm_mma<<<dim3(NT_R1, BB / 128), 256, GEMM_SMEM>>>(
        Ar1, 2 * KP_R1, 8, (const char*)Wr1p, br1, nullptr, r1, RR1, 1);
    conv_plain<<<(int)(((size_t)BB * KP_R2 + 255) / 256), 256>>>(r1, RR1, KP_R2, BB, Ar2);
    gemm_mma<<<dim3(NT_R2, BB / 128), 256, GEMM_SMEM>>>(
        Ar2, 2 * KP_R2, 9, (const char*)Wr2p, br2, nullptr, r2, RR2, 1);
    conv_plain<<<(int)(((size_t)BB * KP_R3 + 255) / 256), 256>>>(r2, RR2, KP_R3, BB, Ar3);
    gemm_mma<<<dim3(NT_R3, BB / 128), 256, GEMM_SMEM>>>(
        Ar3, 2 * KP_R3, 6, (const char*)Wr3p, br3, nullptr, out, TT, 0);
}